// round 15
// baseline (speedup 1.0000x reference)
#include <cuda_runtime.h>

#define Nn 8192
#define Dd 16
#define Cc 8
#define Rr 64
#define NROWS (Cc + Dd * (Cc + 1))   // 152

// fp32 score scratch: 8192*152*4B = ~5 MB (static device global, allowed)
__device__ float g_scores[(size_t)Nn * NROWS];

// ---------------------------------------------------------------------------
// Kernel A: new_emb[n,r] = sum_d alpha[n,d]*msg[n,d,r] + curr_emb[n,0,r]
// Triggers PDL at start (single wave) so kernel B can begin streaming its
// A-independent data concurrently.
// ---------------------------------------------------------------------------
__global__ __launch_bounds__(256) void new_emb_kernel(
    const float* __restrict__ msg,
    const float* __restrict__ alpha,
    const float* __restrict__ curr_emb,
    float* __restrict__ out_emb)
{
#if __CUDA_ARCH__ >= 900
    cudaTriggerProgrammaticLaunchCompletion();
#endif
    const int idx = blockIdx.x * 256 + threadIdx.x;   // 0 .. N*R/2-1
    const int n  = idx >> 5;                          // 32 pairs per n
    const int p  = idx & 31;                          // r-pair index

    const float2* m2 = (const float2*)(msg + (size_t)n * Dd * Rr) + p;
    const float*  a  = alpha + (size_t)n * Dd;

    float2 acc = make_float2(0.f, 0.f);
    #pragma unroll
    for (int d = 0; d < Dd; d++) {
        const float2 mv = m2[d * (Rr / 2)];
        const float  ad = a[d];
        acc.x += ad * mv.x;
        acc.y += ad * mv.y;
    }
    const float2 ce = ((const float2*)(curr_emb + (size_t)n * Dd * Rr))[p];
    acc.x += ce.x;  acc.y += ce.y;
    ((float2*)out_emb)[idx] = acc;
}

// ---------------------------------------------------------------------------
// Kernel B: warp = 4 rows, 8-lane groups, contiguous float4 loads.
// PDL secondary: issues all A-independent loads, then grid-dependency-sync,
// then consumes new_emb. __ldcs on zero-reuse pa/pb streams.
// ---------------------------------------------------------------------------
__global__ __launch_bounds__(256) void score_kernel(
    const float* __restrict__ curr_node_mem,
    const float* __restrict__ curr_rel_mem,
    const float* __restrict__ nei_node_mem,
    const float* __restrict__ nei_rel_mem,
    const float* __restrict__ head_rel_emb,
    const float* __restrict__ head_emb,
    const float* __restrict__ new_emb)
{
    const int gw   = (blockIdx.x * 256 + threadIdx.x) >> 5;
    const int lane = threadIdx.x & 31;
    const int sub  = lane >> 3;
    const int sl   = lane & 7;

    const int row = gw * 4 + sub;            // exact cover: 152 % 4 == 0
    const int n   = row / NROWS;
    const int j   = row - n * NROWS;

    const size_t baseDR  = (size_t)n * Dd * Rr;
    const size_t baseDCR = (size_t)n * Dd * Cc * Rr;

    const float4* pa;
    const float4* pb = nullptr;
    const float4* ph = nullptr;
    if (j < Cc) {
        pa = (const float4*)(curr_node_mem + baseDCR + (size_t)j * Rr);
        pb = (const float4*)(curr_rel_mem  + baseDCR + (size_t)j * Rr);
    } else {
        const int j2 = j - Cc;
        const int d  = j2 / 9;
        const int cc = j2 - d * 9;
        ph = (const float4*)(head_rel_emb + baseDR + (size_t)d * Rr);
        if (cc < Cc) {
            pa = (const float4*)(nei_node_mem + baseDCR + (size_t)(d * Cc + cc) * Rr);
            pb = (const float4*)(nei_rel_mem  + baseDCR + (size_t)(d * Cc + cc) * Rr);
        } else {
            pa = (const float4*)(head_emb + baseDR + (size_t)d * Rr);
        }
    }

    // A-independent loads first (overlap with kernel A under PDL)
    const float4 a0 = __ldcs(&pa[sl]);
    const float4 a1 = __ldcs(&pa[8 + sl]);
    float4 b0 = make_float4(0.f, 0.f, 0.f, 0.f);
    float4 b1 = make_float4(0.f, 0.f, 0.f, 0.f);
    if (pb) { b0 = __ldcs(&pb[sl]); b1 = __ldcs(&pb[8 + sl]); }
    float4 h0 = make_float4(0.f, 0.f, 0.f, 0.f);
    float4 h1 = make_float4(0.f, 0.f, 0.f, 0.f);
    if (ph) { h0 = ph[sl]; h1 = ph[8 + sl]; }

    // wait for kernel A's new_emb to be visible
#if __CUDA_ARCH__ >= 900
    cudaGridDependencySynchronize();
#endif
    const float4* pn = (const float4*)(new_emb + (size_t)n * Rr);
    const float4 ne0 = pn[sl];
    const float4 ne1 = pn[8 + sl];

    float d0 = (a0.x + (b0.x + h0.x)) - ne0.x;
    float d1 = (a0.y + (b0.y + h0.y)) - ne0.y;
    float d2 = (a0.z + (b0.z + h0.z)) - ne0.z;
    float d3 = (a0.w + (b0.w + h0.w)) - ne0.w;
    float d4 = (a1.x + (b1.x + h1.x)) - ne1.x;
    float d5 = (a1.y + (b1.y + h1.y)) - ne1.y;
    float d6 = (a1.z + (b1.z + h1.z)) - ne1.z;
    float d7 = (a1.w + (b1.w + h1.w)) - ne1.w;

    float q0 = fmaf(d0, d0, d1 * d1);
    float q1 = fmaf(d2, d2, d3 * d3);
    float q2 = fmaf(d4, d4, d5 * d5);
    float q3 = fmaf(d6, d6, d7 * d7);
    float s  = (q0 + q1) + (q2 + q3);

    s += __shfl_down_sync(0xffffffffu, s, 4);
    s += __shfl_down_sync(0xffffffffu, s, 2);
    s += __shfl_down_sync(0xffffffffu, s, 1);
    if (sl == 0) g_scores[row] = s;

#if __CUDA_ARCH__ >= 900
    cudaTriggerProgrammaticLaunchCompletion();
#endif
}

// ---------------------------------------------------------------------------
// Kernel C: one WARP per n. PDL secondary (ramp overlap with B's drain).
// ---------------------------------------------------------------------------
__global__ __launch_bounds__(512) void topk_gather_kernel(
    const float* __restrict__ curr_node_mem,
    const float* __restrict__ curr_rel_mem,
    const float* __restrict__ nei_node_mem,
    const float* __restrict__ nei_rel_mem,
    const float* __restrict__ head_rel_emb,
    const float* __restrict__ head_emb,
    float* __restrict__ out_node,
    float* __restrict__ out_rel)
{
#if __CUDA_ARCH__ >= 900
    cudaGridDependencySynchronize();
#endif
    const int n    = blockIdx.x * 16 + (threadIdx.x >> 5);
    const int lane = threadIdx.x & 31;

    // load this n's 152 scores: lane holds j = lane + 32*i
    float v[5];
    #pragma unroll
    for (int i = 0; i < 5; i++) {
        const int j = lane + 32 * i;
        v[i] = (j < NROWS) ? g_scores[(size_t)n * NROWS + j] : -3.0f;
    }

    // 8x stable warp arg-max (max score, tie -> lower index)
    int sel[Cc];
    #pragma unroll
    for (int k = 0; k < Cc; k++) {
        float bs = -1.0f;
        int   bj = NROWS;
        #pragma unroll
        for (int i = 0; i < 5; i++) {
            const int j = lane + 32 * i;
            if (v[i] > bs || (v[i] == bs && j < bj)) { bs = v[i]; bj = j; }
        }
        #pragma unroll
        for (int off = 16; off; off >>= 1) {
            float os = __shfl_down_sync(0xffffffffu, bs, off);
            int   oj = __shfl_down_sync(0xffffffffu, bj, off);
            if (os > bs || (os == bs && oj < bj)) { bs = os; bj = oj; }
        }
        bj = __shfl_sync(0xffffffffu, bj, 0);
        sel[k] = bj;
        if ((bj & 31) == lane) v[bj >> 5] = -2.0f;   // remove winner
    }

    // gather: this warp writes its 8 output rows
    // reference: f = n*C + topkind; nn = f/152, col = f%152 (cross-sample)
    #pragma unroll
    for (int k = 0; k < Cc; k++) {
        const int f   = n * Cc + sel[k];
        const int nn  = f / NROWS;
        const int col = f - nn * NROWS;
        const size_t gDR  = (size_t)nn * Dd * Rr;
        const size_t gDCR = (size_t)nn * Dd * Cc * Rr;

        float2 a, b;
        if (col < Cc) {
            a = ((const float2*)(curr_node_mem + gDCR + (size_t)col * Rr))[lane];
            b = ((const float2*)(curr_rel_mem  + gDCR + (size_t)col * Rr))[lane];
        } else {
            int c2 = col - Cc;
            int d  = c2 / 9;
            int cc = c2 - d * 9;
            float2 h = ((const float2*)(head_rel_emb + gDR + (size_t)d * Rr))[lane];
            if (cc < Cc) {
                a = ((const float2*)(nei_node_mem + gDCR + (size_t)(d * Cc + cc) * Rr))[lane];
                float2 bb = ((const float2*)(nei_rel_mem + gDCR + (size_t)(d * Cc + cc) * Rr))[lane];
                b.x = bb.x + h.x;  b.y = bb.y + h.y;
            } else {
                a = ((const float2*)(head_emb + gDR + (size_t)d * Rr))[lane];
                b = h;
            }
        }
        ((float2*)(out_node + ((size_t)n * Cc + k) * Rr))[lane] = a;
        ((float2*)(out_rel  + ((size_t)n * Cc + k) * Rr))[lane] = b;
    }
}

// ---------------------------------------------------------------------------
extern "C" void kernel_launch(void* const* d_in, const int* in_sizes, int n_in,
                              void* d_out, int out_size)
{
    (void)in_sizes; (void)n_in; (void)out_size;
    const float* curr_emb      = (const float*)d_in[0];
    const float* alpha         = (const float*)d_in[1];
    const float* msg           = (const float*)d_in[2];
    const float* curr_node_mem = (const float*)d_in[3];
    const float* curr_rel_mem  = (const float*)d_in[4];
    const float* nei_node_mem  = (const float*)d_in[5];
    const float* nei_rel_mem   = (const float*)d_in[6];
    const float* head_rel_emb  = (const float*)d_in[7];
    const float* head_emb      = (const float*)d_in[8];

    float* out_emb  = (float*)d_out;                     // N*R
    float* out_node = out_emb  + (size_t)Nn * Rr;        // N*C*R
    float* out_rel  = out_node + (size_t)Nn * Cc * Rr;   // N*C*R

    // A: new_emb (normal launch; triggers PDL early)
    new_emb_kernel<<<(Nn * Rr / 2) / 256, 256>>>(msg, alpha, curr_emb, out_emb);

    // B: scores — PDL secondary of A
    {
        cudaLaunchConfig_t cfg = {};
        cfg.gridDim  = dim3((Nn * NROWS / 4) / 8, 1, 1);   // 38912 blocks
        cfg.blockDim = dim3(256, 1, 1);
        cudaLaunchAttribute attr[1];
        attr[0].id = cudaLaunchAttributeProgrammaticStreamSerialization;
        attr[0].val.programmaticStreamSerializationAllowed = 1;
        cfg.attrs = attr;
        cfg.numAttrs = 1;
        cudaLaunchKernelEx(&cfg, score_kernel,
                           curr_node_mem, curr_rel_mem,
                           nei_node_mem, nei_rel_mem,
                           head_rel_emb, head_emb,
                           (const float*)out_emb);
    }

    // C: topk + gather — PDL secondary of B (ramp overlap only)
    {
        cudaLaunchConfig_t cfg = {};
        cfg.gridDim  = dim3(Nn / 16, 1, 1);
        cfg.blockDim = dim3(512, 1, 1);
        cudaLaunchAttribute attr[1];
        attr[0].id = cudaLaunchAttributeProgrammaticStreamSerialization;
        attr[0].val.programmaticStreamSerializationAllowed = 1;
        cfg.attrs = attr;
        cfg.numAttrs = 1;
        cudaLaunchKernelEx(&cfg, topk_gather_kernel,
                           curr_node_mem, curr_rel_mem,
                           nei_node_mem, nei_rel_mem,
                           head_rel_emb, head_emb,
                           out_node, out_rel);
    }
}

// round 16
// speedup vs baseline: 1.0439x; 1.0439x over previous
#include <cuda_runtime.h>

#define Nn 8192
#define Dd 16
#define Cc 8
#define Rr 64
#define NROWS (Cc + Dd * (Cc + 1))   // 152

// fp32 score scratch: 8192*152*4B = ~5 MB (static device global, allowed)
__device__ float g_scores[(size_t)Nn * NROWS];

// ---------------------------------------------------------------------------
// Kernel A: new_emb[n,r] = sum_d alpha[n,d]*msg[n,d,r] + curr_emb[n,0,r]
// ---------------------------------------------------------------------------
__global__ __launch_bounds__(256) void new_emb_kernel(
    const float* __restrict__ msg,
    const float* __restrict__ alpha,
    const float* __restrict__ curr_emb,
    float* __restrict__ out_emb)
{
    const int idx = blockIdx.x * 256 + threadIdx.x;   // 0 .. N*R/2-1
    const int n  = idx >> 5;                          // 32 pairs per n
    const int p  = idx & 31;                          // r-pair index

    const float2* m2 = (const float2*)(msg + (size_t)n * Dd * Rr) + p;
    const float*  a  = alpha + (size_t)n * Dd;

    float2 acc = make_float2(0.f, 0.f);
    #pragma unroll
    for (int d = 0; d < Dd; d++) {
        const float2 mv = m2[d * (Rr / 2)];
        const float  ad = a[d];
        acc.x += ad * mv.x;
        acc.y += ad * mv.y;
    }
    const float2 ce = ((const float2*)(curr_emb + (size_t)n * Dd * Rr))[p];
    acc.x += ce.x;  acc.y += ce.y;
    ((float2*)out_emb)[idx] = acc;
}

// ---------------------------------------------------------------------------
// Kernel B (champion): warp = 4 rows, 8-lane groups, contiguous float4 loads.
// __ldcs (evict-first) on the zero-reuse pa/pb streams; default policy on the
// reused ph (head_rel, 9x per n) and pn (new_emb, 38x per n) loads.
// fp32 tree + fp32 3-step combine.
// ---------------------------------------------------------------------------
__global__ __launch_bounds__(256) void score_kernel(
    const float* __restrict__ curr_node_mem,
    const float* __restrict__ curr_rel_mem,
    const float* __restrict__ nei_node_mem,
    const float* __restrict__ nei_rel_mem,
    const float* __restrict__ head_rel_emb,
    const float* __restrict__ head_emb,
    const float* __restrict__ new_emb)
{
    const int gw   = (blockIdx.x * 256 + threadIdx.x) >> 5;
    const int lane = threadIdx.x & 31;
    const int sub  = lane >> 3;
    const int sl   = lane & 7;

    const int row = gw * 4 + sub;            // exact cover: 152 % 4 == 0
    const int n   = row / NROWS;
    const int j   = row - n * NROWS;

    const size_t baseDR  = (size_t)n * Dd * Rr;
    const size_t baseDCR = (size_t)n * Dd * Cc * Rr;

    const float4* pa;
    const float4* pb = nullptr;
    const float4* ph = nullptr;
    if (j < Cc) {
        pa = (const float4*)(curr_node_mem + baseDCR + (size_t)j * Rr);
        pb = (const float4*)(curr_rel_mem  + baseDCR + (size_t)j * Rr);
    } else {
        const int j2 = j - Cc;
        const int d  = j2 / 9;
        const int cc = j2 - d * 9;
        ph = (const float4*)(head_rel_emb + baseDR + (size_t)d * Rr);
        if (cc < Cc) {
            pa = (const float4*)(nei_node_mem + baseDCR + (size_t)(d * Cc + cc) * Rr);
            pb = (const float4*)(nei_rel_mem  + baseDCR + (size_t)(d * Cc + cc) * Rr);
        } else {
            pa = (const float4*)(head_emb + baseDR + (size_t)d * Rr);
        }
    }

    const float4* pn = (const float4*)(new_emb + (size_t)n * Rr);
    const float4 ne0 = pn[sl];
    const float4 ne1 = pn[8 + sl];
    const float4 a0  = __ldcs(&pa[sl]);
    const float4 a1  = __ldcs(&pa[8 + sl]);
    float4 b0 = make_float4(0.f, 0.f, 0.f, 0.f);
    float4 b1 = make_float4(0.f, 0.f, 0.f, 0.f);
    if (pb) { b0 = __ldcs(&pb[sl]); b1 = __ldcs(&pb[8 + sl]); }
    float4 h0 = make_float4(0.f, 0.f, 0.f, 0.f);
    float4 h1 = make_float4(0.f, 0.f, 0.f, 0.f);
    if (ph) { h0 = ph[sl]; h1 = ph[8 + sl]; }

    float d0 = (a0.x + (b0.x + h0.x)) - ne0.x;
    float d1 = (a0.y + (b0.y + h0.y)) - ne0.y;
    float d2 = (a0.z + (b0.z + h0.z)) - ne0.z;
    float d3 = (a0.w + (b0.w + h0.w)) - ne0.w;
    float d4 = (a1.x + (b1.x + h1.x)) - ne1.x;
    float d5 = (a1.y + (b1.y + h1.y)) - ne1.y;
    float d6 = (a1.z + (b1.z + h1.z)) - ne1.z;
    float d7 = (a1.w + (b1.w + h1.w)) - ne1.w;

    float q0 = fmaf(d0, d0, d1 * d1);
    float q1 = fmaf(d2, d2, d3 * d3);
    float q2 = fmaf(d4, d4, d5 * d5);
    float q3 = fmaf(d6, d6, d7 * d7);
    float s  = (q0 + q1) + (q2 + q3);

    s += __shfl_down_sync(0xffffffffu, s, 4);
    s += __shfl_down_sync(0xffffffffu, s, 2);
    s += __shfl_down_sync(0xffffffffu, s, 1);
    if (sl == 0) g_scores[row] = s;
}

// ---------------------------------------------------------------------------
// Kernel C: one WARP per n. Streaming stores on the never-re-read outputs
// (protects the L2-resident gather-source region). 16 warps/block.
// ---------------------------------------------------------------------------
__global__ __launch_bounds__(512) void topk_gather_kernel(
    const float* __restrict__ curr_node_mem,
    const float* __restrict__ curr_rel_mem,
    const float* __restrict__ nei_node_mem,
    const float* __restrict__ nei_rel_mem,
    const float* __restrict__ head_rel_emb,
    const float* __restrict__ head_emb,
    float* __restrict__ out_node,
    float* __restrict__ out_rel)
{
    const int n    = blockIdx.x * 16 + (threadIdx.x >> 5);
    const int lane = threadIdx.x & 31;

    // load this n's 152 scores: lane holds j = lane + 32*i
    float v[5];
    #pragma unroll
    for (int i = 0; i < 5; i++) {
        const int j = lane + 32 * i;
        v[i] = (j < NROWS) ? g_scores[(size_t)n * NROWS + j] : -3.0f;
    }

    // 8x stable warp arg-max (max score, tie -> lower index)
    int sel[Cc];
    #pragma unroll
    for (int k = 0; k < Cc; k++) {
        float bs = -1.0f;
        int   bj = NROWS;
        #pragma unroll
        for (int i = 0; i < 5; i++) {
            const int j = lane + 32 * i;
            if (v[i] > bs || (v[i] == bs && j < bj)) { bs = v[i]; bj = j; }
        }
        #pragma unroll
        for (int off = 16; off; off >>= 1) {
            float os = __shfl_down_sync(0xffffffffu, bs, off);
            int   oj = __shfl_down_sync(0xffffffffu, bj, off);
            if (os > bs || (os == bs && oj < bj)) { bs = os; bj = oj; }
        }
        bj = __shfl_sync(0xffffffffu, bj, 0);
        sel[k] = bj;
        if ((bj & 31) == lane) v[bj >> 5] = -2.0f;   // remove winner
    }

    // gather: this warp writes its 8 output rows
    // reference: f = n*C + topkind; nn = f/152, col = f%152 (cross-sample)
    #pragma unroll
    for (int k = 0; k < Cc; k++) {
        const int f   = n * Cc + sel[k];
        const int nn  = f / NROWS;
        const int col = f - nn * NROWS;
        const size_t gDR  = (size_t)nn * Dd * Rr;
        const size_t gDCR = (size_t)nn * Dd * Cc * Rr;

        float2 a, b;
        if (col < Cc) {
            a = ((const float2*)(curr_node_mem + gDCR + (size_t)col * Rr))[lane];
            b = ((const float2*)(curr_rel_mem  + gDCR + (size_t)col * Rr))[lane];
        } else {
            int c2 = col - Cc;
            int d  = c2 / 9;
            int cc = c2 - d * 9;
            float2 h = ((const float2*)(head_rel_emb + gDR + (size_t)d * Rr))[lane];
            if (cc < Cc) {
                a = ((const float2*)(nei_node_mem + gDCR + (size_t)(d * Cc + cc) * Rr))[lane];
                float2 bb = ((const float2*)(nei_rel_mem + gDCR + (size_t)(d * Cc + cc) * Rr))[lane];
                b.x = bb.x + h.x;  b.y = bb.y + h.y;
            } else {
                a = ((const float2*)(head_emb + gDR + (size_t)d * Rr))[lane];
                b = h;
            }
        }
        __stcs((float2*)(out_node + ((size_t)n * Cc + k) * Rr) + lane, a);
        __stcs((float2*)(out_rel  + ((size_t)n * Cc + k) * Rr) + lane, b);
    }
}

// ---------------------------------------------------------------------------
extern "C" void kernel_launch(void* const* d_in, const int* in_sizes, int n_in,
                              void* d_out, int out_size)
{
    (void)in_sizes; (void)n_in; (void)out_size;
    const float* curr_emb      = (const float*)d_in[0];
    const float* alpha         = (const float*)d_in[1];
    const float* msg           = (const float*)d_in[2];
    const float* curr_node_mem = (const float*)d_in[3];
    const float* curr_rel_mem  = (const float*)d_in[4];
    const float* nei_node_mem  = (const float*)d_in[5];
    const float* nei_rel_mem   = (const float*)d_in[6];
    const float* head_rel_emb  = (const float*)d_in[7];
    const float* head_emb      = (const float*)d_in[8];

    float* out_emb  = (float*)d_out;                     // N*R
    float* out_node = out_emb  + (size_t)Nn * Rr;        // N*C*R
    float* out_rel  = out_node + (size_t)Nn * Cc * Rr;   // N*C*R

    // A: new_emb (thread per float2)
    new_emb_kernel<<<(Nn * Rr / 2) / 256, 256>>>(msg, alpha, curr_emb, out_emb);

    // B: scores (warp = 4 rows; exact cover)
    const int total_warps = (Nn * NROWS) / 4;            // 311296
    score_kernel<<<total_warps / 8, 256>>>(curr_node_mem, curr_rel_mem,
                                           nei_node_mem, nei_rel_mem,
                                           head_rel_emb, head_emb, out_emb);

    // C: topk + gather, one warp per n, 16 warps/block
    topk_gather_kernel<<<Nn / 16, 512>>>(curr_node_mem, curr_rel_mem,
                                         nei_node_mem, nei_rel_mem,
                                         head_rel_emb, head_emb,
                                         out_node, out_rel);
}